// round 8
// baseline (speedup 1.0000x reference)
#include <cuda_runtime.h>
#include <cuda_fp16.h>
#include <math.h>

#define NPTS   8192
#define MPTS   8192
#define NB     16
#define WIDTH  32
#define NSPLIT 19
#define TILE_J 128
#define IBLK   256

// Per-source packed record: x, y, z, wrho, bp[16]  (bp = -beta * log2(e))
__device__ float g_packed[NPTS * 20];
__device__ float g_heg[NB];
__device__ float g_partial[(size_t)NSPLIT * MPTS * NB];

// ---- raw MUFU helpers ----
__device__ __forceinline__ float f_ex2(float x) {
    float r; asm("ex2.approx.f32 %0, %1;" : "=f"(r) : "f"(x)); return r;
}
__device__ __forceinline__ float f_lg2(float x) {
    float r; asm("lg2.approx.f32 %0, %1;" : "=f"(r) : "f"(x)); return r;
}
__device__ __forceinline__ float f_rcp(float x) {
    float r; asm("rcp.approx.f32 %0, %1;" : "=f"(r) : "f"(x)); return r;
}
__device__ __forceinline__ float fast_tanh(float a) {
    float u = f_ex2(2.885390081777927f * a);   // exp(2a)
    return fmaf(-2.0f, f_rcp(u + 1.0f), 1.0f);
}
__device__ __forceinline__ float fast_log_cosh(float t) {
    const float LN2 = 0.69314718055994531f;
    float a = fabsf(t);
    float v = f_ex2(-2.885390081777927f * a);  // exp(-2a)
    return fmaf(f_lg2(1.0f + v), LN2, a - LN2);
}

// Warp-per-point setup: lane k owns hidden unit k; WIDTH->NB layer via
// 32 SHFL broadcasts; lane b<16 owns basis b.
__global__ void __launch_bounds__(256)
setup_kernel(const float* __restrict__ rho,
             const float* __restrict__ gamma,
             const float* __restrict__ coords,
             const float* __restrict__ weights,
             const float* __restrict__ w1,
             const float* __restrict__ b1,
             const float* __restrict__ w2,
             const float* __restrict__ b2) {
    __shared__ float s_w2[WIDTH * NB];
    int tid = threadIdx.x;
    for (int v = tid; v < WIDTH * NB; v += blockDim.x) s_w2[v] = w2[v];
    __syncthreads();

    int lane = tid & 31;
    int warp = tid >> 5;
    int j = blockIdx.x * (blockDim.x >> 5) + warp;
    if (j >= NPTS) return;

    const float C     = 38.283120002509214f;   // 4*(3*pi^2)^(2/3)
    const float LOG2E = 1.44269504088896340f;
    const float LN2   = 0.69314718055994531f;

    float r = rho[j];
    float l = f_lg2(r);
    float r83 = r * r * f_ex2(l * (2.0f / 3.0f));          // r^(8/3)
    float s2 = gamma[j] * f_rcp(C * r83);
    float x = f_lg2(s2 + 1e-4f) * LN2;                     // log(s2+eps)

    // hidden layer: one tanh per lane
    float h = fast_tanh(fmaf(x, w1[lane], b1[lane]));

    // output layer: lane b (b<16) accumulates o_b
    int bl = lane & (NB - 1);
    float o = b2[bl];
#pragma unroll
    for (int k = 0; k < WIDTH; k++) {
        float hk = __shfl_sync(0xffffffffu, h, k);
        o = fmaf(hk, s_w2[k * NB + bl], o);
    }

    float pref = 3.14159265358979323846f * f_ex2((l - 1.0f) * (2.0f / 3.0f));
    float bp = -pref * fast_log_cosh(o) * LOG2E;

    if (lane < NB) g_packed[j * 20 + 4 + lane] = bp;
    if (lane == 16) g_packed[j * 20 + 0] = coords[j * 3 + 0];
    if (lane == 17) g_packed[j * 20 + 1] = coords[j * 3 + 1];
    if (lane == 18) g_packed[j * 20 + 2] = coords[j * 3 + 2];
    if (lane == 19) g_packed[j * 20 + 3] = weights[j] * r;

    if (j == 0) {
        // heg_scale: field_embed at x = 0
        float h0 = fast_tanh(b1[lane]);
        float o0 = b2[bl];
#pragma unroll
        for (int k = 0; k < WIDTH; k++) {
            float hk = __shfl_sync(0xffffffffu, h0, k);
            o0 = fmaf(hk, s_w2[k * NB + bl], o0);
        }
        if (lane < NB) {
            float lc = fast_log_cosh(o0);
            g_heg[lane] = lc * sqrtf(lc);                  // lc^1.5
        }
    }
}

__global__ void __launch_bounds__(IBLK)
main_kernel(const float* __restrict__ out_coords) {
    __shared__ float tile[TILE_J * 20];

    int i = blockIdx.x * IBLK + threadIdx.x;
    int split = blockIdx.y;

    float ox = out_coords[i * 3 + 0];
    float oy = out_coords[i * 3 + 1];
    float oz = out_coords[i * 3 + 2];

    float acc[NB];
#pragma unroll
    for (int b = 0; b < NB; b++) acc[b] = 0.0f;

    int jbeg = (split * NPTS) / NSPLIT;
    int jend = ((split + 1) * NPTS) / NSPLIT;

    for (int t = jbeg; t < jend; t += TILE_J) {
        int cnt = min(TILE_J, jend - t);
        __syncthreads();
        {
            const float4* src = (const float4*)(g_packed + (size_t)t * 20);
            float4* dst = (float4*)tile;
            int nvec = cnt * 5;  // 20 floats = 5 float4 per j
            for (int v = threadIdx.x; v < nvec; v += IBLK) dst[v] = src[v];
        }
        __syncthreads();

        for (int jt = 0; jt < cnt; ++jt) {
            const float* p = tile + jt * 20;
            float4 cw = *(const float4*)p;  // x, y, z, wrho
            float dx = ox - cw.x;
            float dy = oy - cw.y;
            float dz = oz - cw.z;
            float d2 = fmaf(dx, dx, fmaf(dy, dy, dz * dz));
            float w = cw.w;
            // args in full f32 (one rounding into f16x2); exp on MUFU as
            // 8x ex2.approx.f16x2 (2 values per MUFU slot); f32 accumulate.
#pragma unroll
            for (int q = 0; q < 8; q++) {
                float a0 = p[4 + 2 * q + 0] * d2;   // -beta*log2e*d2
                float a1 = p[4 + 2 * q + 1] * d2;
                __half2 hh = __floats2half2_rn(a0, a1);
                __half2 ee = h2exp2(hh);
                float2 ef = __half22float2(ee);
                acc[2 * q + 0] = fmaf(ef.x, w, acc[2 * q + 0]);
                acc[2 * q + 1] = fmaf(ef.y, w, acc[2 * q + 1]);
            }
        }
    }

    float* outp = g_partial + ((size_t)split * MPTS + i) * NB;
#pragma unroll
    for (int b = 0; b < NB; b++) outp[b] = acc[b];
}

__global__ void reduce_kernel(float* __restrict__ out) {
    int idx = blockIdx.x * blockDim.x + threadIdx.x;  // i*NB + b
    if (idx >= MPTS * NB) return;
    int b = idx & (NB - 1);
    float s = 0.0f;
#pragma unroll
    for (int sp = 0; sp < NSPLIT; sp++)
        s += g_partial[(size_t)sp * (MPTS * NB) + idx];
    out[idx] = s * g_heg[b];
}

extern "C" void kernel_launch(void* const* d_in, const int* in_sizes, int n_in,
                              void* d_out, int out_size) {
    const float* rho        = (const float*)d_in[0];
    const float* gamma      = (const float*)d_in[1];
    const float* coords     = (const float*)d_in[2];
    const float* weights    = (const float*)d_in[3];
    const float* out_coords = (const float*)d_in[4];
    const float* w1         = (const float*)d_in[5];
    const float* b1         = (const float*)d_in[6];
    const float* w2         = (const float*)d_in[7];
    const float* b2         = (const float*)d_in[8];
    float* out = (float*)d_out;

    setup_kernel<<<NPTS / 8, 256>>>(rho, gamma, coords, weights,
                                    w1, b1, w2, b2);
    dim3 grid(MPTS / IBLK, NSPLIT);
    main_kernel<<<grid, IBLK>>>(out_coords);
    reduce_kernel<<<(MPTS * NB + 255) / 256, 256>>>(out);
}

// round 9
// speedup vs baseline: 1.8380x; 1.8380x over previous
#include <cuda_runtime.h>
#include <cuda_fp16.h>
#include <math.h>

#define NPTS   8192
#define MPTS   8192
#define NB     16
#define WIDTH  32
#define NSPLIT 19
#define TILE_J 128
#define IBLK   256
#define REC    12   // x, y, z, w_h2(u32), bp_h2[8](u32)

__device__ float g_packed[NPTS * REC];
__device__ float g_heg[NB];
__device__ float g_partial[(size_t)NSPLIT * MPTS * NB];

// ---- raw MUFU helpers ----
__device__ __forceinline__ float f_ex2(float x) {
    float r; asm("ex2.approx.f32 %0, %1;" : "=f"(r) : "f"(x)); return r;
}
__device__ __forceinline__ float f_lg2(float x) {
    float r; asm("lg2.approx.f32 %0, %1;" : "=f"(r) : "f"(x)); return r;
}
__device__ __forceinline__ float f_rcp(float x) {
    float r; asm("rcp.approx.f32 %0, %1;" : "=f"(r) : "f"(x)); return r;
}
__device__ __forceinline__ float fast_tanh(float a) {
    float u = f_ex2(2.885390081777927f * a);   // exp(2a)
    return fmaf(-2.0f, f_rcp(u + 1.0f), 1.0f);
}
__device__ __forceinline__ float fast_log_cosh(float t) {
    const float LN2 = 0.69314718055994531f;
    float a = fabsf(t);
    float v = f_ex2(-2.885390081777927f * a);  // exp(-2a)
    return fmaf(f_lg2(1.0f + v), LN2, a - LN2);
}

// Guaranteed single-op f16x2 exp2 on MUFU (two values per MUFU slot).
__device__ __forceinline__ unsigned h2ex2_raw(unsigned x) {
    unsigned r;
    asm("ex2.approx.f16x2 %0, %1;" : "=r"(r) : "r"(x));
    return r;
}

// Warp-per-point setup: lane k owns hidden unit k; WIDTH->NB layer via
// 32 SHFL broadcasts; lane b<16 owns basis b. Packs bp into half2 pairs.
__global__ void __launch_bounds__(256)
setup_kernel(const float* __restrict__ rho,
             const float* __restrict__ gamma,
             const float* __restrict__ coords,
             const float* __restrict__ weights,
             const float* __restrict__ w1,
             const float* __restrict__ b1,
             const float* __restrict__ w2,
             const float* __restrict__ b2) {
    __shared__ float s_w2[WIDTH * NB];
    int tid = threadIdx.x;
    for (int v = tid; v < WIDTH * NB; v += blockDim.x) s_w2[v] = w2[v];
    __syncthreads();

    int lane = tid & 31;
    int warp = tid >> 5;
    int j = blockIdx.x * (blockDim.x >> 5) + warp;
    if (j >= NPTS) return;

    const float C     = 38.283120002509214f;   // 4*(3*pi^2)^(2/3)
    const float LOG2E = 1.44269504088896340f;
    const float LN2   = 0.69314718055994531f;

    float r = rho[j];
    float l = f_lg2(r);
    float r83 = r * r * f_ex2(l * (2.0f / 3.0f));          // r^(8/3)
    float s2 = gamma[j] * f_rcp(C * r83);
    float x = f_lg2(s2 + 1e-4f) * LN2;                     // log(s2+eps)

    float h = fast_tanh(fmaf(x, w1[lane], b1[lane]));

    int bl = lane & (NB - 1);
    float o = b2[bl];
#pragma unroll
    for (int k = 0; k < WIDTH; k++) {
        float hk = __shfl_sync(0xffffffffu, h, k);
        o = fmaf(hk, s_w2[k * NB + bl], o);
    }

    float pref = 3.14159265358979323846f * f_ex2((l - 1.0f) * (2.0f / 3.0f));
    float bp = -pref * fast_log_cosh(o) * LOG2E;

    // pack channel pairs (2q, 2q+1) into half2
    float bpn = __shfl_down_sync(0xffffffffu, bp, 1);
    if (lane < NB && (lane & 1) == 0) {
        __half2 hh = __floats2half2_rn(bp, bpn);
        ((unsigned*)g_packed)[j * REC + 4 + (lane >> 1)] =
            *(unsigned*)&hh;
    }
    if (lane == 16) g_packed[j * REC + 0] = coords[j * 3 + 0];
    if (lane == 17) g_packed[j * REC + 1] = coords[j * 3 + 1];
    if (lane == 18) g_packed[j * REC + 2] = coords[j * 3 + 2];
    if (lane == 19) {
        __half2 wh = __float2half2_rn(weights[j] * r);
        ((unsigned*)g_packed)[j * REC + 3] = *(unsigned*)&wh;
    }

    if (j == 0) {
        float h0 = fast_tanh(b1[lane]);
        float o0 = b2[bl];
#pragma unroll
        for (int k = 0; k < WIDTH; k++) {
            float hk = __shfl_sync(0xffffffffu, h0, k);
            o0 = fmaf(hk, s_w2[k * NB + bl], o0);
        }
        if (lane < NB) {
            float lc = fast_log_cosh(o0);
            g_heg[lane] = lc * sqrtf(lc);                  // lc^1.5
        }
    }
}

__global__ void __launch_bounds__(IBLK)
main_kernel(const float* __restrict__ out_coords) {
    __shared__ float tile[TILE_J * REC];

    int i = blockIdx.x * IBLK + threadIdx.x;
    int split = blockIdx.y;

    float ox = out_coords[i * 3 + 0];
    float oy = out_coords[i * 3 + 1];
    float oz = out_coords[i * 3 + 2];

    float acc[NB];
#pragma unroll
    for (int b = 0; b < NB; b++) acc[b] = 0.0f;

    int jbeg = (split * NPTS) / NSPLIT;
    int jend = ((split + 1) * NPTS) / NSPLIT;

    for (int t = jbeg; t < jend; t += TILE_J) {
        int cnt = min(TILE_J, jend - t);
        __syncthreads();
        {
            const float4* src = (const float4*)(g_packed + (size_t)t * REC);
            float4* dst = (float4*)tile;
            int nvec = cnt * (REC / 4);   // 3 float4 per j
            for (int v = threadIdx.x; v < nvec; v += IBLK) dst[v] = src[v];
        }
        __syncthreads();

        for (int j0 = 0; j0 < cnt; j0 += 16) {
            int jn = min(16, cnt - j0);
            // half2 partial accumulators (<=16 terms, each <=0.2: no overflow)
            __half2 hacc[8];
#pragma unroll
            for (int q = 0; q < 8; q++) hacc[q] = __float2half2_rn(0.0f);

            for (int jt = j0; jt < j0 + jn; ++jt) {
                const float* p = tile + jt * REC;
                float4 cw = *(const float4*)p;   // x, y, z, w_h2(bits)
                float dx = ox - cw.x;
                float dy = oy - cw.y;
                float dz = oz - cw.z;
                float d2 = fmaf(dx, dx, fmaf(dy, dy, dz * dz));
                __half2 d2h = __float2half2_rn(d2);      // one F2FP
                __half2 wh = *(__half2*)&cw.w;
                const __half2* bp = (const __half2*)(p + 4);
#pragma unroll
                for (int q = 0; q < 8; q++) {
                    __half2 arg = __hmul2(bp[q], d2h);   // HMUL2 (fma pipe)
                    unsigned eu = h2ex2_raw(*(unsigned*)&arg); // 1 MUFU slot, 2 exps
                    hacc[q] = __hfma2(*(__half2*)&eu, wh, hacc[q]);
                }
            }
            // flush to f32
#pragma unroll
            for (int q = 0; q < 8; q++) {
                float2 f = __half22float2(hacc[q]);
                acc[2 * q + 0] += f.x;
                acc[2 * q + 1] += f.y;
            }
        }
    }

    float* outp = g_partial + ((size_t)split * MPTS + i) * NB;
#pragma unroll
    for (int b = 0; b < NB; b++) outp[b] = acc[b];
}

__global__ void reduce_kernel(float* __restrict__ out) {
    int idx = blockIdx.x * blockDim.x + threadIdx.x;  // i*NB + b
    if (idx >= MPTS * NB) return;
    int b = idx & (NB - 1);
    float s = 0.0f;
#pragma unroll
    for (int sp = 0; sp < NSPLIT; sp++)
        s += g_partial[(size_t)sp * (MPTS * NB) + idx];
    out[idx] = s * g_heg[b];
}

extern "C" void kernel_launch(void* const* d_in, const int* in_sizes, int n_in,
                              void* d_out, int out_size) {
    const float* rho        = (const float*)d_in[0];
    const float* gamma      = (const float*)d_in[1];
    const float* coords     = (const float*)d_in[2];
    const float* weights    = (const float*)d_in[3];
    const float* out_coords = (const float*)d_in[4];
    const float* w1         = (const float*)d_in[5];
    const float* b1         = (const float*)d_in[6];
    const float* w2         = (const float*)d_in[7];
    const float* b2         = (const float*)d_in[8];
    float* out = (float*)d_out;

    setup_kernel<<<NPTS / 8, 256>>>(rho, gamma, coords, weights,
                                    w1, b1, w2, b2);
    dim3 grid(MPTS / IBLK, NSPLIT);
    main_kernel<<<grid, IBLK>>>(out_coords);
    reduce_kernel<<<(MPTS * NB + 255) / 256, 256>>>(out);
}